// round 1
// baseline (speedup 1.0000x reference)
#include <cuda_runtime.h>
#include <math.h>

#define NB 8
#define CCH 256
#define HW 4096
#define EPSF 1e-6f

// ---- scratch (device globals; no runtime allocation) ----
__device__ float g_ymu[CCH];
__device__ float g_xn[(size_t)NB * HW * CCH];   // [n][i][c] normalized x
__device__ float g_yn[(size_t)NB * HW * CCH];   // [n][j][c] normalized y
__device__ float g_D[(size_t)NB * HW * HW];     // d matrix, later overwritten with ccx_ij
__device__ float g_accum[NB];

// ---------------- K0: zero accumulators ----------------
__global__ void k_zero() {
    if (threadIdx.x < NB) g_accum[threadIdx.x] = 0.0f;
}

// ---------------- K1: per-channel mean of y ----------------
__global__ void k_ymu(const float* __restrict__ y) {
    int c = blockIdx.x;
    float s = 0.0f;
    for (int n = 0; n < NB; n++) {
        const float* p = y + ((size_t)n * CCH + c) * HW;
        for (int t = threadIdx.x; t < HW; t += 256) s += p[t];
    }
    __shared__ float sh[256];
    sh[threadIdx.x] = s;
    __syncthreads();
    for (int o = 128; o > 0; o >>= 1) {
        if (threadIdx.x < o) sh[threadIdx.x] += sh[threadIdx.x + o];
        __syncthreads();
    }
    if (threadIdx.x == 0) g_ymu[c] = sh[0] * (1.0f / (NB * HW));
}

// ---------------- K2: center + L2-normalize over C, transpose to [n][pos][c] ----------------
// grid: (HW/32, NB, 2)  block: 256
__global__ void k_norm(const float* __restrict__ x, const float* __restrict__ y) {
    const float* src = blockIdx.z ? y : x;
    float* dst = blockIdx.z ? g_yn : g_xn;
    int n = blockIdx.y;
    int i0 = blockIdx.x * 32;

    __shared__ float sh[32 * 257];
    __shared__ float inv[32];

    const float* base = src + (size_t)n * CCH * HW + i0;
    int tid = threadIdx.x;
    int p = tid & 31, cl = tid >> 5;  // 32 positions x 8 channel-lanes

    for (int cc = cl; cc < CCH; cc += 8) {
        sh[p * 257 + cc] = base[(size_t)cc * HW + p] - g_ymu[cc];
    }
    __syncthreads();
    if (tid < 32) {
        float ss = 0.0f;
        #pragma unroll 8
        for (int c = 0; c < CCH; c++) {
            float v = sh[tid * 257 + c];
            ss += v * v;
        }
        inv[tid] = 1.0f / sqrtf(ss);
    }
    __syncthreads();
    float* out = dst + ((size_t)n * HW + i0) * CCH;
    for (int idx = tid; idx < 32 * CCH; idx += 256) {
        int pp = idx >> 8, c = idx & 255;
        out[idx] = sh[pp * 257 + c] * inv[pp];
    }
}

// ---------------- K3: GEMM  D[n][i][j] = 1 - sum_c A[i][c]*B[j][c] ----------------
// grid: (32, 32, NB)  block: 256. 128x128 tile, BK=16, 8x8 per thread.
__global__ void __launch_bounds__(256, 2) k_gemm() {
    int nIdx = blockIdx.z;
    int i0 = blockIdx.x * 128, j0 = blockIdx.y * 128;
    const float* A = g_xn + (size_t)nIdx * HW * CCH;
    const float* B = g_yn + (size_t)nIdx * HW * CCH;
    float* D = g_D + (size_t)nIdx * HW * HW;

    __shared__ float As[16][128];
    __shared__ float Bs[16][128];

    int tid = threadIdx.x;
    int tx = tid & 15, ty = tid >> 4;

    float acc[8][8];
    #pragma unroll
    for (int a = 0; a < 8; a++)
        #pragma unroll
        for (int b = 0; b < 8; b++) acc[a][b] = 0.0f;

    for (int k0 = 0; k0 < CCH; k0 += 16) {
        #pragma unroll
        for (int s = 0; s < 2; s++) {
            int slot = tid + s * 256;
            int row = slot >> 2, kq = slot & 3;
            float4 a4 = *(const float4*)(A + (size_t)(i0 + row) * CCH + k0 + kq * 4);
            As[kq * 4 + 0][row] = a4.x;
            As[kq * 4 + 1][row] = a4.y;
            As[kq * 4 + 2][row] = a4.z;
            As[kq * 4 + 3][row] = a4.w;
            float4 b4 = *(const float4*)(B + (size_t)(j0 + row) * CCH + k0 + kq * 4);
            Bs[kq * 4 + 0][row] = b4.x;
            Bs[kq * 4 + 1][row] = b4.y;
            Bs[kq * 4 + 2][row] = b4.z;
            Bs[kq * 4 + 3][row] = b4.w;
        }
        __syncthreads();
        #pragma unroll
        for (int k = 0; k < 16; k++) {
            float ra[8], rb[8];
            *(float4*)(ra) = *(const float4*)&As[k][ty * 4];
            *(float4*)(ra + 4) = *(const float4*)&As[k][64 + ty * 4];
            *(float4*)(rb) = *(const float4*)&Bs[k][tx * 4];
            *(float4*)(rb + 4) = *(const float4*)&Bs[k][64 + tx * 4];
            #pragma unroll
            for (int a = 0; a < 8; a++)
                #pragma unroll
                for (int b = 0; b < 8; b++)
                    acc[a][b] += ra[a] * rb[b];
        }
        __syncthreads();
    }

    #pragma unroll
    for (int a = 0; a < 8; a++) {
        int r = i0 + ((a < 4) ? (ty * 4 + a) : (64 + ty * 4 + a - 4));
        float4 o;
        o.x = 1.0f - acc[a][0];
        o.y = 1.0f - acc[a][1];
        o.z = 1.0f - acc[a][2];
        o.w = 1.0f - acc[a][3];
        *(float4*)&D[(size_t)r * HW + j0 + tx * 4] = o;
        o.x = 1.0f - acc[a][4];
        o.y = 1.0f - acc[a][5];
        o.z = 1.0f - acc[a][6];
        o.w = 1.0f - acc[a][7];
        *(float4*)&D[(size_t)r * HW + j0 + 64 + tx * 4] = o;
    }
}

// ---------------- K4: per-row min -> w=exp(2-2*d/(dmin+eps)) -> normalize by row sum ----------------
// grid: (HW, NB)  block: 256
__global__ void k_row() {
    size_t base = ((size_t)blockIdx.y * HW + blockIdx.x) * HW;
    float* row = g_D + base;
    int tid = threadIdx.x;
    float v[16];
    float mn = 3.4e38f;
    #pragma unroll
    for (int t = 0; t < 16; t++) {
        v[t] = row[t * 256 + tid];
        mn = fminf(mn, v[t]);
    }
    __shared__ float sh[256];
    sh[tid] = mn;
    __syncthreads();
    for (int o = 128; o > 0; o >>= 1) {
        if (tid < o) sh[tid] = fminf(sh[tid], sh[tid + o]);
        __syncthreads();
    }
    float scale = 2.0f / (sh[0] + EPSF);
    __syncthreads();

    float s = 0.0f;
    #pragma unroll
    for (int t = 0; t < 16; t++) {
        v[t] = expf(2.0f - v[t] * scale);
        s += v[t];
    }
    sh[tid] = s;
    __syncthreads();
    for (int o = 128; o > 0; o >>= 1) {
        if (tid < o) sh[tid] += sh[tid + o];
        __syncthreads();
    }
    float invS = 1.0f / sh[0];
    #pragma unroll
    for (int t = 0; t < 16; t++) row[t * 256 + tid] = v[t] * invS;
}

// ---------------- K5: column max over i, then sum over j into g_accum[n] ----------------
// grid: (16, NB)  block: 1024
__global__ void k_colmax() {
    int n = blockIdx.y;
    int j0 = blockIdx.x * 256;
    int tid = threadIdx.x;
    int jl = tid & 255, q = tid >> 8;
    const float* W = g_D + (size_t)n * HW * HW + j0 + jl;
    float m = -3.4e38f;
    #pragma unroll 4
    for (int i = q; i < HW; i += 4)
        m = fmaxf(m, W[(size_t)i * HW]);

    __shared__ float sm[1024];
    sm[q * 256 + jl] = m;
    __syncthreads();
    if (tid < 256) {
        float mm = fmaxf(fmaxf(sm[tid], sm[256 + tid]), fmaxf(sm[512 + tid], sm[768 + tid]));
        sm[tid] = mm;
    }
    __syncthreads();
    for (int o = 128; o > 0; o >>= 1) {
        if (tid < o) sm[tid] += sm[tid + o];
        __syncthreads();
    }
    if (tid == 0) atomicAdd(&g_accum[n], sm[0]);
}

// ---------------- K6: final loss ----------------
__global__ void k_final(float* __restrict__ out) {
    if (threadIdx.x == 0) {
        float s = 0.0f;
        for (int n = 0; n < NB; n++)
            s += -logf(g_accum[n] * (1.0f / HW) + EPSF);
        out[0] = s * (1.0f / NB);
    }
}

extern "C" void kernel_launch(void* const* d_in, const int* in_sizes, int n_in,
                              void* d_out, int out_size) {
    const float* x = (const float*)d_in[0];
    const float* y = (const float*)d_in[1];
    float* out = (float*)d_out;

    k_zero<<<1, 32>>>();
    k_ymu<<<CCH, 256>>>(y);
    k_norm<<<dim3(HW / 32, NB, 2), 256>>>(x, y);
    k_gemm<<<dim3(32, 32, NB), 256>>>();
    k_row<<<dim3(HW, NB), 256>>>();
    k_colmax<<<dim3(16, NB), 1024>>>();
    k_final<<<1, 32>>>(out);
}

// round 3
// speedup vs baseline: 2.8383x; 2.8383x over previous
#include <cuda_runtime.h>
#include <cuda_bf16.h>
#include <math.h>
#include <stdint.h>

#define NB 8
#define CCH 256
#define HW 4096
#define EPSF 1e-6f

// ---- scratch (device globals; no runtime allocation) ----
__device__ float g_ymu[CCH];
__device__ __nv_bfloat16 g_xn[(size_t)NB * HW * CCH];   // [n][i][c] normalized x (bf16)
__device__ __nv_bfloat16 g_yn[(size_t)NB * HW * CCH];   // [n][j][c] normalized y (bf16)
__device__ float g_D[(size_t)NB * HW * HW];             // d matrix -> ccx_ij
__device__ float g_accum[NB];

__device__ __forceinline__ uint32_t smem_u32(const void* p) {
    uint32_t a;
    asm("{ .reg .u64 t; cvta.to.shared.u64 t, %1; cvt.u32.u64 %0, t; }" : "=r"(a) : "l"(p));
    return a;
}
__device__ __forceinline__ void mma_bf16(float* c, const uint32_t* a, const uint32_t* b) {
    asm volatile(
        "mma.sync.aligned.m16n8k16.row.col.f32.bf16.bf16.f32 "
        "{%0,%1,%2,%3}, {%4,%5,%6,%7}, {%8,%9}, {%0,%1,%2,%3};"
        : "+f"(c[0]), "+f"(c[1]), "+f"(c[2]), "+f"(c[3])
        : "r"(a[0]), "r"(a[1]), "r"(a[2]), "r"(a[3]), "r"(b[0]), "r"(b[1]));
}
__device__ __forceinline__ void ldsm_x4(uint32_t* r, uint32_t addr) {
    asm volatile("ldmatrix.sync.aligned.m8n8.x4.shared.b16 {%0,%1,%2,%3}, [%4];"
                 : "=r"(r[0]), "=r"(r[1]), "=r"(r[2]), "=r"(r[3]) : "r"(addr));
}
#define CP_ASYNC(dst, src) \
    asm volatile("cp.async.cg.shared.global [%0], [%1], 16;" :: "r"(dst), "l"(src))
#define CP_COMMIT() asm volatile("cp.async.commit_group;" ::: "memory")
#define CP_WAIT(n) asm volatile("cp.async.wait_group %0;" :: "n"(n) : "memory")

// swizzled smem offset: 64B rows, 16B chunks, chunk ^= (row>>1)&3
__device__ __forceinline__ uint32_t swz(int row, int ch) {
    return (uint32_t)(row * 64 + ((ch ^ ((row >> 1) & 3)) << 4));
}

// ---------------- K0 ----------------
__global__ void k_zero() {
    if (threadIdx.x < NB) g_accum[threadIdx.x] = 0.0f;
}

// ---------------- K1: per-channel mean of y ----------------
__global__ void k_ymu(const float* __restrict__ y) {
    int c = blockIdx.x;
    float s = 0.0f;
    for (int n = 0; n < NB; n++) {
        const float* p = y + ((size_t)n * CCH + c) * HW;
        for (int t = threadIdx.x; t < HW; t += 256) s += p[t];
    }
    __shared__ float sh[256];
    sh[threadIdx.x] = s;
    __syncthreads();
    for (int o = 128; o > 0; o >>= 1) {
        if (threadIdx.x < o) sh[threadIdx.x] += sh[threadIdx.x + o];
        __syncthreads();
    }
    if (threadIdx.x == 0) g_ymu[c] = sh[0] * (1.0f / (NB * HW));
}

// ---------------- K2: center + normalize over C, transpose, store bf16 ----------------
__global__ void k_norm(const float* __restrict__ x, const float* __restrict__ y) {
    const float* src = blockIdx.z ? y : x;
    __nv_bfloat16* dst = blockIdx.z ? g_yn : g_xn;
    int n = blockIdx.y;
    int i0 = blockIdx.x * 32;

    __shared__ float sh[32 * 257];
    __shared__ float inv[32];

    const float* base = src + (size_t)n * CCH * HW + i0;
    int tid = threadIdx.x;
    int p = tid & 31, cl = tid >> 5;

    for (int cc = cl; cc < CCH; cc += 8)
        sh[p * 257 + cc] = base[(size_t)cc * HW + p] - g_ymu[cc];
    __syncthreads();
    if (tid < 32) {
        float ss = 0.0f;
        #pragma unroll 8
        for (int c = 0; c < CCH; c++) {
            float v = sh[tid * 257 + c];
            ss += v * v;
        }
        inv[tid] = 1.0f / sqrtf(ss);
    }
    __syncthreads();
    __nv_bfloat16* out = dst + ((size_t)n * HW + i0) * CCH;
    for (int idx = tid; idx < 32 * CCH; idx += 256) {
        int pp = idx >> 8, c = idx & 255;
        out[idx] = __float2bfloat16(sh[pp * 257 + c] * inv[pp]);
    }
}

// ---------------- K3: HMMA bf16 GEMM, D = 1 - A·B^T ----------------
// grid (32, 32, NB), block 256 (8 warps: 4 in M x 2 in N), CTA tile 128x128, BK=32
__global__ void __launch_bounds__(256) k_gemm_mma() {
    __shared__ __align__(16) char smem[4 * 8192];   // As[2] then Bs[2]

    int tid = threadIdx.x;
    int wid = tid >> 5, lane = tid & 31;
    int wm = wid >> 1, wn = wid & 1;

    int n = blockIdx.z;
    int i0 = blockIdx.x * 128, j0 = blockIdx.y * 128;

    const __nv_bfloat16* A = g_xn + ((size_t)n * HW + i0) * CCH;
    const __nv_bfloat16* B = g_yn + ((size_t)n * HW + j0) * CCH;

    uint32_t sbase = smem_u32(smem);

    // global->smem loader offsets for this thread (2 chunks each for A and B)
    int r0 = tid >> 2, c0 = tid & 3;            // idx = tid
    int r1 = (tid + 256) >> 2, c1 = tid & 3;    // idx = tid + 256
    uint32_t dA0 = swz(r0, c0), dA1 = swz(r1, c1);

    float acc[2][8][4];
    #pragma unroll
    for (int mf = 0; mf < 2; mf++)
        #pragma unroll
        for (int nf = 0; nf < 8; nf++)
            #pragma unroll
            for (int q = 0; q < 4; q++) acc[mf][nf][q] = 0.0f;

    // ldmatrix per-thread source rows
    int rowA[2], cAbase;
    {
        int m_in = lane & 15;
        cAbase = lane >> 4;                     // 0 or 1
        rowA[0] = wm * 32 + m_in;
        rowA[1] = wm * 32 + 16 + m_in;
    }
    int rowB[4], cBbase;
    {
        int grp = lane >> 3;                    // 0..3
        int n_off = (grp >> 1) * 8;
        cBbase = grp & 1;
        #pragma unroll
        for (int g = 0; g < 4; g++)
            rowB[g] = wn * 64 + g * 16 + n_off + (lane & 7);
    }

    // prologue: stage 0
    {
        const __nv_bfloat16* a0 = A + (size_t)r0 * CCH + c0 * 8;
        const __nv_bfloat16* a1 = A + (size_t)r1 * CCH + c1 * 8;
        const __nv_bfloat16* b0 = B + (size_t)r0 * CCH + c0 * 8;
        const __nv_bfloat16* b1 = B + (size_t)r1 * CCH + c1 * 8;
        CP_ASYNC(sbase + dA0, a0);
        CP_ASYNC(sbase + dA1, a1);
        CP_ASYNC(sbase + 16384 + dA0, b0);
        CP_ASYNC(sbase + 16384 + dA1, b1);
        CP_COMMIT();
    }

    #pragma unroll 1
    for (int s = 0; s < 8; s++) {
        if (s + 1 < 8) {
            int k0 = (s + 1) * 32;
            uint32_t so = ((s + 1) & 1) * 8192;
            const __nv_bfloat16* a0 = A + (size_t)r0 * CCH + k0 + c0 * 8;
            const __nv_bfloat16* a1 = A + (size_t)r1 * CCH + k0 + c1 * 8;
            const __nv_bfloat16* b0 = B + (size_t)r0 * CCH + k0 + c0 * 8;
            const __nv_bfloat16* b1 = B + (size_t)r1 * CCH + k0 + c1 * 8;
            CP_ASYNC(sbase + so + dA0, a0);
            CP_ASYNC(sbase + so + dA1, a1);
            CP_ASYNC(sbase + 16384 + so + dA0, b0);
            CP_ASYNC(sbase + 16384 + so + dA1, b1);
            CP_COMMIT();
            CP_WAIT(1);
        } else {
            CP_WAIT(0);
        }
        __syncthreads();

        uint32_t sA = sbase + (s & 1) * 8192;
        uint32_t sB = sbase + 16384 + (s & 1) * 8192;

        #pragma unroll
        for (int t = 0; t < 2; t++) {           // two k16 steps in the 32-wide stage
            int kc = t * 2;                      // chunk offset for this k-step
            uint32_t a[2][4];
            #pragma unroll
            for (int mf = 0; mf < 2; mf++) {
                int row = rowA[mf];
                uint32_t addr = sA + (uint32_t)(row * 64 + (((cAbase + kc) ^ ((row >> 1) & 3)) << 4));
                ldsm_x4(a[mf], addr);
            }
            uint32_t breg[16];
            #pragma unroll
            for (int g = 0; g < 4; g++) {
                int row = rowB[g];
                uint32_t addr = sB + (uint32_t)(row * 64 + (((cBbase + kc) ^ ((row >> 1) & 3)) << 4));
                ldsm_x4(breg + g * 4, addr);
            }
            #pragma unroll
            for (int mf = 0; mf < 2; mf++)
                #pragma unroll
                for (int nf = 0; nf < 8; nf++)
                    mma_bf16(acc[mf][nf], a[mf], breg + ((nf >> 1) * 4 + (nf & 1) * 2));
        }
        __syncthreads();
    }

    // epilogue: D = 1 - acc
    float* Dn = g_D + (size_t)n * HW * HW;
    int rbase = i0 + wm * 32 + (lane >> 2);
    int cbase = j0 + wn * 64 + (lane & 3) * 2;
    #pragma unroll
    for (int mf = 0; mf < 2; mf++) {
        #pragma unroll
        for (int nf = 0; nf < 8; nf++) {
            int col = cbase + nf * 8;
            int ra = rbase + mf * 16;
            float2 v0 = make_float2(1.0f - acc[mf][nf][0], 1.0f - acc[mf][nf][1]);
            float2 v1 = make_float2(1.0f - acc[mf][nf][2], 1.0f - acc[mf][nf][3]);
            *reinterpret_cast<float2*>(Dn + (size_t)ra * HW + col) = v0;
            *reinterpret_cast<float2*>(Dn + (size_t)(ra + 8) * HW + col) = v1;
        }
    }
}

// ---------------- K4: row pass ----------------
__global__ void k_row() {
    size_t base = ((size_t)blockIdx.y * HW + blockIdx.x) * HW;
    float* row = g_D + base;
    int tid = threadIdx.x;
    float v[16];
    float mn = 3.4e38f;
    #pragma unroll
    for (int t = 0; t < 16; t++) {
        v[t] = row[t * 256 + tid];
        mn = fminf(mn, v[t]);
    }
    __shared__ float sh[256];
    sh[tid] = mn;
    __syncthreads();
    for (int o = 128; o > 0; o >>= 1) {
        if (tid < o) sh[tid] = fminf(sh[tid], sh[tid + o]);
        __syncthreads();
    }
    float scale = 2.0f / (sh[0] + EPSF);
    __syncthreads();

    float s = 0.0f;
    #pragma unroll
    for (int t = 0; t < 16; t++) {
        v[t] = expf(2.0f - v[t] * scale);
        s += v[t];
    }
    sh[tid] = s;
    __syncthreads();
    for (int o = 128; o > 0; o >>= 1) {
        if (tid < o) sh[tid] += sh[tid + o];
        __syncthreads();
    }
    float invS = 1.0f / sh[0];
    #pragma unroll
    for (int t = 0; t < 16; t++) row[t * 256 + tid] = v[t] * invS;
}

// ---------------- K5: column max + sum ----------------
__global__ void k_colmax() {
    int n = blockIdx.y;
    int j0 = blockIdx.x * 256;
    int tid = threadIdx.x;
    int jl = tid & 255, q = tid >> 8;
    const float* W = g_D + (size_t)n * HW * HW + j0 + jl;
    float m = -3.4e38f;
    #pragma unroll 4
    for (int i = q; i < HW; i += 4)
        m = fmaxf(m, W[(size_t)i * HW]);

    __shared__ float sm[1024];
    sm[q * 256 + jl] = m;
    __syncthreads();
    if (tid < 256) {
        float mm = fmaxf(fmaxf(sm[tid], sm[256 + tid]), fmaxf(sm[512 + tid], sm[768 + tid]));
        sm[tid] = mm;
    }
    __syncthreads();
    for (int o = 128; o > 0; o >>= 1) {
        if (tid < o) sm[tid] += sm[tid + o];
        __syncthreads();
    }
    if (tid == 0) atomicAdd(&g_accum[n], sm[0]);
}

// ---------------- K6: final loss ----------------
__global__ void k_final(float* __restrict__ out) {
    if (threadIdx.x == 0) {
        float s = 0.0f;
        for (int n = 0; n < NB; n++)
            s += -logf(g_accum[n] * (1.0f / HW) + EPSF);
        out[0] = s * (1.0f / NB);
    }
}

extern "C" void kernel_launch(void* const* d_in, const int* in_sizes, int n_in,
                              void* d_out, int out_size) {
    const float* x = (const float*)d_in[0];
    const float* y = (const float*)d_in[1];
    float* out = (float*)d_out;

    k_zero<<<1, 32>>>();
    k_ymu<<<CCH, 256>>>(y);
    k_norm<<<dim3(HW / 32, NB, 2), 256>>>(x, y);
    k_gemm_mma<<<dim3(HW / 128, HW / 128, NB), 256>>>();
    k_row<<<dim3(HW, NB), 256>>>();
    k_colmax<<<dim3(16, NB), 1024>>>();
    k_final<<<1, 32>>>(out);
}

// round 4
// speedup vs baseline: 3.4316x; 1.2090x over previous
#include <cuda_runtime.h>
#include <cuda_bf16.h>
#include <cuda_fp16.h>
#include <math.h>
#include <stdint.h>

#define NB 8
#define CCH 256
#define HW 4096
#define EPSF 1e-6f

// ---- scratch (device globals; no runtime allocation) ----
__device__ float g_ymu[CCH];
__device__ __nv_bfloat16 g_xn[(size_t)NB * HW * CCH];   // [n][i][c] normalized x (bf16)
__device__ __nv_bfloat16 g_yn[(size_t)NB * HW * CCH];   // [n][j][c] normalized y (bf16)
__device__ __half g_D[(size_t)NB * HW * HW];            // d matrix (fp16, 256 MB)
__device__ float2 g_ab[(size_t)NB * HW];                // per-row (a, b): w/S = exp(b - a*d)
__device__ float g_accum[NB];

__device__ __forceinline__ uint32_t smem_u32(const void* p) {
    uint32_t a;
    asm("{ .reg .u64 t; cvta.to.shared.u64 t, %1; cvt.u32.u64 %0, t; }" : "=r"(a) : "l"(p));
    return a;
}
__device__ __forceinline__ void mma_bf16(float* c, const uint32_t* a, const uint32_t* b) {
    asm volatile(
        "mma.sync.aligned.m16n8k16.row.col.f32.bf16.bf16.f32 "
        "{%0,%1,%2,%3}, {%4,%5,%6,%7}, {%8,%9}, {%0,%1,%2,%3};"
        : "+f"(c[0]), "+f"(c[1]), "+f"(c[2]), "+f"(c[3])
        : "r"(a[0]), "r"(a[1]), "r"(a[2]), "r"(a[3]), "r"(b[0]), "r"(b[1]));
}
__device__ __forceinline__ void ldsm_x4(uint32_t* r, uint32_t addr) {
    asm volatile("ldmatrix.sync.aligned.m8n8.x4.shared.b16 {%0,%1,%2,%3}, [%4];"
                 : "=r"(r[0]), "=r"(r[1]), "=r"(r[2]), "=r"(r[3]) : "r"(addr));
}
#define CP_ASYNC(dst, src) \
    asm volatile("cp.async.cg.shared.global [%0], [%1], 16;" :: "r"(dst), "l"(src))
#define CP_COMMIT() asm volatile("cp.async.commit_group;" ::: "memory")
#define CP_WAIT(n) asm volatile("cp.async.wait_group %0;" :: "n"(n) : "memory")

// swizzled smem offset: 64B rows, 16B chunks, chunk ^= (row>>1)&3
__device__ __forceinline__ uint32_t swz(int row, int ch) {
    return (uint32_t)(row * 64 + ((ch ^ ((row >> 1) & 3)) << 4));
}

// ---------------- K0 ----------------
__global__ void k_zero() {
    if (threadIdx.x < NB) g_accum[threadIdx.x] = 0.0f;
}

// ---------------- K1: per-channel mean of y ----------------
__global__ void k_ymu(const float* __restrict__ y) {
    int c = blockIdx.x;
    float s = 0.0f;
    for (int n = 0; n < NB; n++) {
        const float* p = y + ((size_t)n * CCH + c) * HW;
        for (int t = threadIdx.x; t < HW; t += 256) s += p[t];
    }
    __shared__ float sh[256];
    sh[threadIdx.x] = s;
    __syncthreads();
    for (int o = 128; o > 0; o >>= 1) {
        if (threadIdx.x < o) sh[threadIdx.x] += sh[threadIdx.x + o];
        __syncthreads();
    }
    if (threadIdx.x == 0) g_ymu[c] = sh[0] * (1.0f / (NB * HW));
}

// ---------------- K2: center + normalize over C, transpose, store bf16 ----------------
__global__ void k_norm(const float* __restrict__ x, const float* __restrict__ y) {
    const float* src = blockIdx.z ? y : x;
    __nv_bfloat16* dst = blockIdx.z ? g_yn : g_xn;
    int n = blockIdx.y;
    int i0 = blockIdx.x * 32;

    __shared__ float sh[32 * 257];
    __shared__ float inv[32];

    const float* base = src + (size_t)n * CCH * HW + i0;
    int tid = threadIdx.x;
    int p = tid & 31, cl = tid >> 5;

    for (int cc = cl; cc < CCH; cc += 8)
        sh[p * 257 + cc] = base[(size_t)cc * HW + p] - g_ymu[cc];
    __syncthreads();
    if (tid < 32) {
        float ss = 0.0f;
        #pragma unroll 8
        for (int c = 0; c < CCH; c++) {
            float v = sh[tid * 257 + c];
            ss += v * v;
        }
        inv[tid] = rsqrtf(ss);
    }
    __syncthreads();
    __nv_bfloat16* out = dst + ((size_t)n * HW + i0) * CCH;
    for (int idx = tid; idx < 32 * CCH; idx += 256) {
        int pp = idx >> 8, c = idx & 255;
        out[idx] = __float2bfloat16(sh[pp * 257 + c] * inv[pp]);
    }
}

// ---------------- K3: HMMA bf16 GEMM, D = 1 - A·B^T (fp16 out), 3-stage pipeline ----------------
// grid (32, 32, NB), block 256 (8 warps: 4 in M x 2 in N), CTA tile 128x128, BK=32
__global__ void __launch_bounds__(256) k_gemm_mma() {
    __shared__ __align__(16) char smem[49152];   // 3 stages x (A 8KB + B 8KB)

    int tid = threadIdx.x;
    int wid = tid >> 5, lane = tid & 31;
    int wm = wid >> 1, wn = wid & 1;

    int n = blockIdx.z;
    int i0 = blockIdx.x * 128, j0 = blockIdx.y * 128;

    const __nv_bfloat16* A = g_xn + ((size_t)n * HW + i0) * CCH;
    const __nv_bfloat16* B = g_yn + ((size_t)n * HW + j0) * CCH;

    uint32_t sbase = smem_u32(smem);
    const uint32_t B_OFF = 24576;

    // loader thread offsets (2 chunks each for A and B per stage)
    int r0 = tid >> 2, c0 = tid & 3;
    int r1 = r0 + 64;
    uint32_t dA0 = swz(r0, c0), dA1 = swz(r1, c0);

    float acc[2][8][4];
    #pragma unroll
    for (int mf = 0; mf < 2; mf++)
        #pragma unroll
        for (int nf = 0; nf < 8; nf++)
            #pragma unroll
            for (int q = 0; q < 4; q++) acc[mf][nf][q] = 0.0f;

    int rowA[2], cAbase;
    {
        int m_in = lane & 15;
        cAbase = lane >> 4;
        rowA[0] = wm * 32 + m_in;
        rowA[1] = wm * 32 + 16 + m_in;
    }
    int rowB[4], cBbase;
    {
        int grp = lane >> 3;
        int n_off = (grp >> 1) * 8;
        cBbase = grp & 1;
        #pragma unroll
        for (int g = 0; g < 4; g++)
            rowB[g] = wn * 64 + g * 16 + n_off + (lane & 7);
    }

    // prologue: prefetch stages 0,1,2
    #pragma unroll
    for (int s = 0; s < 3; s++) {
        int k0 = s * 32;
        uint32_t so = (uint32_t)s * 8192;
        CP_ASYNC(sbase + so + dA0, A + (size_t)r0 * CCH + k0 + c0 * 8);
        CP_ASYNC(sbase + so + dA1, A + (size_t)r1 * CCH + k0 + c0 * 8);
        CP_ASYNC(sbase + B_OFF + so + dA0, B + (size_t)r0 * CCH + k0 + c0 * 8);
        CP_ASYNC(sbase + B_OFF + so + dA1, B + (size_t)r1 * CCH + k0 + c0 * 8);
        CP_COMMIT();
    }

    #pragma unroll 1
    for (int s = 0; s < 8; s++) {
        CP_WAIT(2);
        __syncthreads();

        int buf = s % 3;
        uint32_t sA = sbase + (uint32_t)buf * 8192;
        uint32_t sB = sbase + B_OFF + (uint32_t)buf * 8192;

        #pragma unroll
        for (int t = 0; t < 2; t++) {
            int kc = t * 2;
            uint32_t a[2][4];
            #pragma unroll
            for (int mf = 0; mf < 2; mf++) {
                int row = rowA[mf];
                uint32_t addr = sA + (uint32_t)(row * 64 + (((cAbase + kc) ^ ((row >> 1) & 3)) << 4));
                ldsm_x4(a[mf], addr);
            }
            uint32_t breg[16];
            #pragma unroll
            for (int g = 0; g < 4; g++) {
                int row = rowB[g];
                uint32_t addr = sB + (uint32_t)(row * 64 + (((cBbase + kc) ^ ((row >> 1) & 3)) << 4));
                ldsm_x4(breg + g * 4, addr);
            }
            #pragma unroll
            for (int mf = 0; mf < 2; mf++)
                #pragma unroll
                for (int nf = 0; nf < 8; nf++)
                    mma_bf16(acc[mf][nf], a[mf], breg + ((nf >> 1) * 4 + (nf & 1) * 2));
        }
        __syncthreads();

        if (s + 3 < 8) {
            int k0 = (s + 3) * 32;
            uint32_t so = (uint32_t)buf * 8192;
            CP_ASYNC(sbase + so + dA0, A + (size_t)r0 * CCH + k0 + c0 * 8);
            CP_ASYNC(sbase + so + dA1, A + (size_t)r1 * CCH + k0 + c0 * 8);
            CP_ASYNC(sbase + B_OFF + so + dA0, B + (size_t)r0 * CCH + k0 + c0 * 8);
            CP_ASYNC(sbase + B_OFF + so + dA1, B + (size_t)r1 * CCH + k0 + c0 * 8);
        }
        CP_COMMIT();
    }

    // epilogue: D = 1 - acc (fp16)
    __half* Dn = g_D + (size_t)n * HW * HW;
    int rbase = i0 + wm * 32 + (lane >> 2);
    int cbase = j0 + wn * 64 + (lane & 3) * 2;
    #pragma unroll
    for (int mf = 0; mf < 2; mf++) {
        #pragma unroll
        for (int nf = 0; nf < 8; nf++) {
            int col = cbase + nf * 8;
            int ra = rbase + mf * 16;
            __half2 h0 = __floats2half2_rn(1.0f - acc[mf][nf][0], 1.0f - acc[mf][nf][1]);
            __half2 h1 = __floats2half2_rn(1.0f - acc[mf][nf][2], 1.0f - acc[mf][nf][3]);
            *reinterpret_cast<__half2*>(Dn + (size_t)ra * HW + col) = h0;
            *reinterpret_cast<__half2*>(Dn + (size_t)(ra + 8) * HW + col) = h1;
        }
    }
}

// ---------------- K4: per-row min + sum -> (a, b) only (no W write) ----------------
// grid (HW, NB), block 256
__global__ void k_minsum() {
    int n = blockIdx.y, i = blockIdx.x;
    const __half2* row = reinterpret_cast<const __half2*>(
        g_D + ((size_t)n * HW + i) * HW);
    int tid = threadIdx.x;

    float2 v[8];
    float mn = 3.4e38f;
    #pragma unroll
    for (int t = 0; t < 8; t++) {
        float2 f = __half22float2(row[t * 256 + tid]);
        v[t] = f;
        mn = fminf(mn, fminf(f.x, f.y));
    }
    __shared__ float sh[256];
    sh[tid] = mn;
    __syncthreads();
    for (int o = 128; o > 0; o >>= 1) {
        if (tid < o) sh[tid] = fminf(sh[tid], sh[tid + o]);
        __syncthreads();
    }
    float a = 2.0f / (sh[0] + EPSF);
    __syncthreads();

    float s = 0.0f;
    #pragma unroll
    for (int t = 0; t < 8; t++)
        s += __expf(2.0f - v[t].x * a) + __expf(2.0f - v[t].y * a);
    sh[tid] = s;
    __syncthreads();
    for (int o = 128; o > 0; o >>= 1) {
        if (tid < o) sh[tid] += sh[tid + o];
        __syncthreads();
    }
    if (tid == 0)
        g_ab[(size_t)n * HW + i] = make_float2(a, 2.0f - __logf(sh[0]));
}

// ---------------- K5: column max of exp(b_i - a_i*d_ij), then sum over j ----------------
// grid (16, NB), block 1024
__global__ void k_colmax() {
    int n = blockIdx.y;
    int j0 = blockIdx.x * 256;
    int tid = threadIdx.x;
    int jl = tid & 255, q = tid >> 8;
    const __half* W = g_D + (size_t)n * HW * HW + j0 + jl;
    const float2* ab = g_ab + (size_t)n * HW;

    float m = 0.0f;
    #pragma unroll 4
    for (int i = q; i < HW; i += 4) {
        float d = __half2float(W[(size_t)i * HW]);
        float2 t = __ldg(&ab[i]);
        m = fmaxf(m, __expf(fmaf(-t.x, d, t.y)));
    }

    __shared__ float sm[1024];
    sm[q * 256 + jl] = m;
    __syncthreads();
    if (tid < 256) {
        float mm = fmaxf(fmaxf(sm[tid], sm[256 + tid]), fmaxf(sm[512 + tid], sm[768 + tid]));
        sm[tid] = mm;
    }
    __syncthreads();
    for (int o = 128; o > 0; o >>= 1) {
        if (tid < o) sm[tid] += sm[tid + o];
        __syncthreads();
    }
    if (tid == 0) atomicAdd(&g_accum[n], sm[0]);
}

// ---------------- K6: final loss ----------------
__global__ void k_final(float* __restrict__ out) {
    if (threadIdx.x == 0) {
        float s = 0.0f;
        for (int n = 0; n < NB; n++)
            s += -logf(g_accum[n] * (1.0f / HW) + EPSF);
        out[0] = s * (1.0f / NB);
    }
}

extern "C" void kernel_launch(void* const* d_in, const int* in_sizes, int n_in,
                              void* d_out, int out_size) {
    const float* x = (const float*)d_in[0];
    const float* y = (const float*)d_in[1];
    float* out = (float*)d_out;

    k_zero<<<1, 32>>>();
    k_ymu<<<CCH, 256>>>(y);
    k_norm<<<dim3(HW / 32, NB, 2), 256>>>(x, y);
    k_gemm_mma<<<dim3(HW / 128, HW / 128, NB), 256>>>();
    k_minsum<<<dim3(HW, NB), 256>>>();
    k_colmax<<<dim3(16, NB), 1024>>>();
    k_final<<<1, 32>>>(out);
}

// round 5
// speedup vs baseline: 4.4563x; 1.2986x over previous
#include <cuda_runtime.h>
#include <cuda_bf16.h>
#include <cuda_fp16.h>
#include <math.h>
#include <stdint.h>

#define NB 8
#define CCH 256
#define HW 4096
#define EPSF 1e-6f

// ---- scratch (device globals; no runtime allocation) ----
__device__ float g_ymu[CCH];
__device__ __nv_bfloat16 g_xn[(size_t)NB * HW * CCH];   // [n][i][c] normalized x (bf16)
__device__ __nv_bfloat16 g_yn[(size_t)NB * HW * CCH];   // [n][j][c] normalized y (bf16)
__device__ __half g_D[(size_t)NB * HW * HW];            // d matrix (fp16, 256 MB)
__device__ float2 g_ab[(size_t)NB * HW];                // per-row (a, b): ccx = exp(b - a*d)
__device__ float g_part[(size_t)NB * 4 * HW];           // partial col-max (linear domain)
__device__ float g_accum[NB];

__device__ __forceinline__ uint32_t smem_u32(const void* p) {
    uint32_t a;
    asm("{ .reg .u64 t; cvta.to.shared.u64 t, %1; cvt.u32.u64 %0, t; }" : "=r"(a) : "l"(p));
    return a;
}
__device__ __forceinline__ void mma_bf16(float* c, const uint32_t* a, const uint32_t* b) {
    asm volatile(
        "mma.sync.aligned.m16n8k16.row.col.f32.bf16.bf16.f32 "
        "{%0,%1,%2,%3}, {%4,%5,%6,%7}, {%8,%9}, {%0,%1,%2,%3};"
        : "+f"(c[0]), "+f"(c[1]), "+f"(c[2]), "+f"(c[3])
        : "r"(a[0]), "r"(a[1]), "r"(a[2]), "r"(a[3]), "r"(b[0]), "r"(b[1]));
}
__device__ __forceinline__ void ldsm_x4(uint32_t* r, uint32_t addr) {
    asm volatile("ldmatrix.sync.aligned.m8n8.x4.shared.b16 {%0,%1,%2,%3}, [%4];"
                 : "=r"(r[0]), "=r"(r[1]), "=r"(r[2]), "=r"(r[3]) : "r"(addr));
}
#define CP_ASYNC(dst, src) \
    asm volatile("cp.async.cg.shared.global [%0], [%1], 16;" :: "r"(dst), "l"(src))
#define CP_COMMIT() asm volatile("cp.async.commit_group;" ::: "memory")
#define CP_WAIT(n) asm volatile("cp.async.wait_group %0;" :: "n"(n) : "memory")

__device__ __forceinline__ uint32_t swz(int row, int ch) {
    return (uint32_t)(row * 64 + ((ch ^ ((row >> 1) & 3)) << 4));
}

// ---------------- K1: per-channel mean of y ----------------
__global__ void k_ymu(const float* __restrict__ y) {
    int c = blockIdx.x;
    float s = 0.0f;
    for (int n = 0; n < NB; n++) {
        const float* p = y + ((size_t)n * CCH + c) * HW;
        for (int t = threadIdx.x; t < HW; t += 256) s += p[t];
    }
    __shared__ float sh[256];
    sh[threadIdx.x] = s;
    __syncthreads();
    for (int o = 128; o > 0; o >>= 1) {
        if (threadIdx.x < o) sh[threadIdx.x] += sh[threadIdx.x + o];
        __syncthreads();
    }
    if (threadIdx.x == 0) g_ymu[c] = sh[0] * (1.0f / (NB * HW));
}

// ---------------- K2: center + normalize over C, transpose, store bf16 ----------------
__global__ void k_norm(const float* __restrict__ x, const float* __restrict__ y) {
    const float* src = blockIdx.z ? y : x;
    __nv_bfloat16* dst = blockIdx.z ? g_yn : g_xn;
    int n = blockIdx.y;
    int i0 = blockIdx.x * 32;

    __shared__ float sh[32 * 257];
    __shared__ float inv[32];

    const float* base = src + (size_t)n * CCH * HW + i0;
    int tid = threadIdx.x;
    int p = tid & 31, cl = tid >> 5;

    for (int cc = cl; cc < CCH; cc += 8)
        sh[p * 257 + cc] = base[(size_t)cc * HW + p] - g_ymu[cc];
    __syncthreads();
    if (tid < 32) {
        float ss = 0.0f;
        #pragma unroll 8
        for (int c = 0; c < CCH; c++) {
            float v = sh[tid * 257 + c];
            ss += v * v;
        }
        inv[tid] = rsqrtf(ss);
    }
    __syncthreads();
    __nv_bfloat16* out = dst + ((size_t)n * HW + i0) * CCH;
    for (int idx = tid; idx < 32 * CCH; idx += 256) {
        int pp = idx >> 8, c = idx & 255;
        out[idx] = __float2bfloat16(sh[pp * 257 + c] * inv[pp]);
    }
}

// ---------------- K3: HMMA bf16 GEMM, D = 1 - A·B^T (fp16 out), 4-stage pipeline ----------------
// grid (32, 32, NB), block 256 (8 warps: 4 in M x 2 in N), CTA tile 128x128, BK=32
__global__ void __launch_bounds__(256, 2) k_gemm_mma() {
    extern __shared__ __align__(16) char smem[];   // 4 stages x (A 8KB) + 4 stages x (B 8KB)

    int tid = threadIdx.x;
    int wid = tid >> 5, lane = tid & 31;
    int wm = wid >> 1, wn = wid & 1;

    int n = blockIdx.z;
    int i0 = blockIdx.x * 128, j0 = blockIdx.y * 128;

    const __nv_bfloat16* A = g_xn + ((size_t)n * HW + i0) * CCH;
    const __nv_bfloat16* B = g_yn + ((size_t)n * HW + j0) * CCH;

    uint32_t sbase = smem_u32(smem);
    const uint32_t B_OFF = 32768;

    int r0 = tid >> 2, c0 = tid & 3;
    int r1 = r0 + 64;
    uint32_t dA0 = swz(r0, c0), dA1 = swz(r1, c0);

    float acc[2][8][4];
    #pragma unroll
    for (int mf = 0; mf < 2; mf++)
        #pragma unroll
        for (int nf = 0; nf < 8; nf++)
            #pragma unroll
            for (int q = 0; q < 4; q++) acc[mf][nf][q] = 0.0f;

    int rowA[2], cAbase;
    {
        int m_in = lane & 15;
        cAbase = lane >> 4;
        rowA[0] = wm * 32 + m_in;
        rowA[1] = wm * 32 + 16 + m_in;
    }
    int rowB[4], cBbase;
    {
        int grp = lane >> 3;
        int n_off = (grp >> 1) * 8;
        cBbase = grp & 1;
        #pragma unroll
        for (int g = 0; g < 4; g++)
            rowB[g] = wn * 64 + g * 16 + n_off + (lane & 7);
    }

    // prologue: prefetch stages 0,1,2
    #pragma unroll
    for (int s = 0; s < 3; s++) {
        int k0 = s * 32;
        uint32_t so = (uint32_t)s * 8192;
        CP_ASYNC(sbase + so + dA0, A + (size_t)r0 * CCH + k0 + c0 * 8);
        CP_ASYNC(sbase + so + dA1, A + (size_t)r1 * CCH + k0 + c0 * 8);
        CP_ASYNC(sbase + B_OFF + so + dA0, B + (size_t)r0 * CCH + k0 + c0 * 8);
        CP_ASYNC(sbase + B_OFF + so + dA1, B + (size_t)r1 * CCH + k0 + c0 * 8);
        CP_COMMIT();
    }

    #pragma unroll 1
    for (int s = 0; s < 8; s++) {
        CP_WAIT(2);
        __syncthreads();

        // issue next stage BEFORE compute (stage s+3 -> buffer (s+3)&3, freed at s-1)
        if (s + 3 < 8) {
            int k0 = (s + 3) * 32;
            uint32_t so = (uint32_t)((s + 3) & 3) * 8192;
            CP_ASYNC(sbase + so + dA0, A + (size_t)r0 * CCH + k0 + c0 * 8);
            CP_ASYNC(sbase + so + dA1, A + (size_t)r1 * CCH + k0 + c0 * 8);
            CP_ASYNC(sbase + B_OFF + so + dA0, B + (size_t)r0 * CCH + k0 + c0 * 8);
            CP_ASYNC(sbase + B_OFF + so + dA1, B + (size_t)r1 * CCH + k0 + c0 * 8);
        }
        CP_COMMIT();

        uint32_t sA = sbase + (uint32_t)(s & 3) * 8192;
        uint32_t sB = sbase + B_OFF + (uint32_t)(s & 3) * 8192;

        #pragma unroll
        for (int t = 0; t < 2; t++) {
            int kc = t * 2;
            uint32_t a[2][4];
            #pragma unroll
            for (int mf = 0; mf < 2; mf++) {
                int row = rowA[mf];
                uint32_t addr = sA + (uint32_t)(row * 64 + (((cAbase + kc) ^ ((row >> 1) & 3)) << 4));
                ldsm_x4(a[mf], addr);
            }
            uint32_t breg[16];
            #pragma unroll
            for (int g = 0; g < 4; g++) {
                int row = rowB[g];
                uint32_t addr = sB + (uint32_t)(row * 64 + (((cBbase + kc) ^ ((row >> 1) & 3)) << 4));
                ldsm_x4(breg + g * 4, addr);
            }
            #pragma unroll
            for (int mf = 0; mf < 2; mf++)
                #pragma unroll
                for (int nf = 0; nf < 8; nf++)
                    mma_bf16(acc[mf][nf], a[mf], breg + ((nf >> 1) * 4 + (nf & 1) * 2));
        }
    }

    // epilogue: D = 1 - acc (fp16)
    __half* Dn = g_D + (size_t)n * HW * HW;
    int rbase = i0 + wm * 32 + (lane >> 2);
    int cbase = j0 + wn * 64 + (lane & 3) * 2;
    #pragma unroll
    for (int mf = 0; mf < 2; mf++) {
        #pragma unroll
        for (int nf = 0; nf < 8; nf++) {
            int col = cbase + nf * 8;
            int ra = rbase + mf * 16;
            __half2 h0 = __floats2half2_rn(1.0f - acc[mf][nf][0], 1.0f - acc[mf][nf][1]);
            __half2 h1 = __floats2half2_rn(1.0f - acc[mf][nf][2], 1.0f - acc[mf][nf][3]);
            *reinterpret_cast<__half2*>(Dn + (size_t)ra * HW + col) = h0;
            *reinterpret_cast<__half2*>(Dn + (size_t)(ra + 8) * HW + col) = h1;
        }
    }
}

// ---------------- K4: warp-per-row min + sum -> (a, b) ----------------
// grid (HW/8, NB), block 256 (8 warps)
__global__ void __launch_bounds__(256) k_minsum() {
    int warp = threadIdx.x >> 5, lane = threadIdx.x & 31;
    int i = blockIdx.x * 8 + warp;
    int n = blockIdx.y;
    const uint4* row = reinterpret_cast<const uint4*>(g_D + ((size_t)n * HW + i) * HW);

    uint4 v[16];
    #pragma unroll
    for (int t = 0; t < 16; t++) v[t] = row[t * 32 + lane];

    __half2 m2 = __floats2half2_rn(6.0e4f, 6.0e4f);
    #pragma unroll
    for (int t = 0; t < 16; t++) {
        const __half2* h = reinterpret_cast<const __half2*>(&v[t]);
        m2 = __hmin2(m2, __hmin2(__hmin2(h[0], h[1]), __hmin2(h[2], h[3])));
    }
    float mn = fminf(__low2float(m2), __high2float(m2));
    #pragma unroll
    for (int o = 16; o > 0; o >>= 1)
        mn = fminf(mn, __shfl_xor_sync(0xffffffff, mn, o));

    float a = 2.0f / (mn + EPSF);
    float s = 0.0f;
    #pragma unroll
    for (int t = 0; t < 16; t++) {
        const __half2* h = reinterpret_cast<const __half2*>(&v[t]);
        #pragma unroll
        for (int q = 0; q < 4; q++) {
            float2 f = __half22float2(h[q]);
            s += __expf(fmaf(-a, f.x, 2.0f)) + __expf(fmaf(-a, f.y, 2.0f));
        }
    }
    #pragma unroll
    for (int o = 16; o > 0; o >>= 1)
        s += __shfl_xor_sync(0xffffffff, s, o);

    if (lane == 0)
        g_ab[(size_t)n * HW + i] = make_float2(a, 2.0f - __logf(s));
}

// ---------------- K5: partial column max of (b_i - a_i*d_ij) over i-chunks ----------------
// grid (8 jb, 4 ic, NB), block 512 (256 j-pairs x 2 i-lanes)
__global__ void __launch_bounds__(512) k_colpart() {
    int n = blockIdx.z, ic = blockIdx.y, jb = blockIdx.x;
    int tid = threadIdx.x;
    int jl = tid & 255, iq = tid >> 8;
    int j = jb * 512 + jl * 2;
    const __half2* W = reinterpret_cast<const __half2*>(g_D + (size_t)n * HW * HW + j);
    const float2* ab = g_ab + (size_t)n * HW;

    float2 m = make_float2(-3.4e38f, -3.4e38f);
    int ibase = ic * 1024;
    #pragma unroll 4
    for (int ii = iq; ii < 1024; ii += 2) {
        int i = ibase + ii;
        float2 f = __half22float2(W[(size_t)i * (HW / 2)]);
        float2 t = __ldg(&ab[i]);
        m.x = fmaxf(m.x, fmaf(-t.x, f.x, t.y));
        m.y = fmaxf(m.y, fmaf(-t.x, f.y, t.y));
    }
    __shared__ float2 sm[512];
    sm[tid] = m;
    __syncthreads();
    if (tid < 256) {
        float2 o = sm[tid + 256];
        m = sm[tid];
        m.x = fmaxf(m.x, o.x);
        m.y = fmaxf(m.y, o.y);
        *reinterpret_cast<float2*>(&g_part[((size_t)n * 4 + ic) * HW + j]) = m;
    }
}

// ---------------- K6: reduce partials: exp(max) summed over j -> g_accum[n] ----------------
// grid (NB), block 1024
__global__ void k_colreduce() {
    int n = blockIdx.x, tid = threadIdx.x;
    float s = 0.0f;
    #pragma unroll
    for (int k = 0; k < 4; k++) {
        int j = tid + k * 1024;
        float m = g_part[((size_t)n * 4 + 0) * HW + j];
        m = fmaxf(m, g_part[((size_t)n * 4 + 1) * HW + j]);
        m = fmaxf(m, g_part[((size_t)n * 4 + 2) * HW + j]);
        m = fmaxf(m, g_part[((size_t)n * 4 + 3) * HW + j]);
        s += __expf(m);
    }
    __shared__ float sh[1024];
    sh[tid] = s;
    __syncthreads();
    for (int o = 512; o > 0; o >>= 1) {
        if (tid < o) sh[tid] += sh[tid + o];
        __syncthreads();
    }
    if (tid == 0) g_accum[n] = sh[0];
}

// ---------------- K7: final loss ----------------
__global__ void k_final(float* __restrict__ out) {
    if (threadIdx.x == 0) {
        float s = 0.0f;
        for (int n = 0; n < NB; n++)
            s += -logf(g_accum[n] * (1.0f / HW) + EPSF);
        out[0] = s * (1.0f / NB);
    }
}

extern "C" void kernel_launch(void* const* d_in, const int* in_sizes, int n_in,
                              void* d_out, int out_size) {
    const float* x = (const float*)d_in[0];
    const float* y = (const float*)d_in[1];
    float* out = (float*)d_out;

    cudaFuncSetAttribute(k_gemm_mma, cudaFuncAttributeMaxDynamicSharedMemorySize, 65536);

    k_ymu<<<CCH, 256>>>(y);
    k_norm<<<dim3(HW / 32, NB, 2), 256>>>(x, y);
    k_gemm_mma<<<dim3(HW / 128, HW / 128, NB), 256, 65536>>>();
    k_minsum<<<dim3(HW / 8, NB), 256>>>();
    k_colpart<<<dim3(8, 4, NB), 512>>>();
    k_colreduce<<<NB, 1024>>>();
    k_final<<<1, 32>>>(out);
}